// round 1
// baseline (speedup 1.0000x reference)
#include <cuda_runtime.h>
#include <math.h>

// Problem constants
#define NPIX      131072          // 4 * (16384 main + 16384 aux)
#define SELBLK    512             // pixels per selection block
#define NBLK      (NPIX / SELBLK) // 256
#define C_CLS     20
#define MEMM      512
#define AROWS     (C_CLS * MEMM)  // 10240
#define DIM       256
#define IGNORE_I  255
#define AUX_I     254

// -------- persistent scratch (device globals; re-initialized every launch) ---
__device__ int   g_blockCounts[NBLK * C_CLS];
__device__ int   g_blockOffsets[NBLK * C_CLS];
__device__ int   g_counts[C_CLS];
__device__ int   g_selIdx[AROWS];
__device__ float g_sel[AROWS * DIM];       // anchors (normalized selected embeddings)
__device__ float g_contras[AROWS * DIM];   // updated memory bank
__device__ float g_cvalid[AROWS];
__device__ int   g_cvSum[C_CLS];
__device__ float g_rowExp[AROWS];
__device__ float g_rowPos[AROWS];

// ----------------------------- helpers --------------------------------------
__device__ __forceinline__ int pix_label(int n, const int* __restrict__ mg,
                                         const int* __restrict__ ag) {
    int b = n >> 15;
    int j = n & 32767;
    int lab;
    if (j < 16384) {
        int h = j >> 7, w = j & 127;
        lab = mg[(b << 18) + (h << 11) + (w << 2)];
    } else {
        int jj = j - 16384;
        int h = jj >> 7, w = jj & 127;
        lab = ag[(b << 18) + (h << 11) + (w << 2)];
    }
    return lab;
}

// ------------------------------ kernels -------------------------------------
__global__ void k_init() {
    int t = blockIdx.x * blockDim.x + threadIdx.x;
    if (t < AROWS) {
        g_selIdx[t] = -1;
        g_rowExp[t] = 0.f;
        g_rowPos[t] = 0.f;
    }
    if (t < C_CLS) g_cvSum[t] = 0;
}

__global__ void k_count(const int* __restrict__ mg, const int* __restrict__ ag) {
    __shared__ int hist[C_CLS];
    if (threadIdx.x < C_CLS) hist[threadIdx.x] = 0;
    __syncthreads();
    int n = blockIdx.x * SELBLK + threadIdx.x;
    int lab = pix_label(n, mg, ag);
    if (lab != IGNORE_I) {
        if (lab == AUX_I) lab = C_CLS - 1;
        atomicAdd(&hist[lab], 1);
    }
    __syncthreads();
    if (threadIdx.x < C_CLS)
        g_blockCounts[blockIdx.x * C_CLS + threadIdx.x] = hist[threadIdx.x];
}

__global__ void k_scan() {
    int c = threadIdx.x;
    if (c >= C_CLS) return;
    int run = 0;
    for (int b = 0; b < NBLK; b++) {
        int t = g_blockCounts[b * C_CLS + c];
        g_blockOffsets[b * C_CLS + c] = run;
        run += t;
    }
    g_counts[c] = run;
}

__global__ void k_select(const int* __restrict__ mg, const int* __restrict__ ag) {
    __shared__ int warpHist[16][C_CLS];
    int tid = threadIdx.x, wid = tid >> 5, lane = tid & 31;
    for (int i = tid; i < 16 * C_CLS; i += SELBLK) ((int*)warpHist)[i] = 0;
    __syncthreads();
    int n = blockIdx.x * SELBLK + tid;
    int lab = pix_label(n, mg, ag);
    bool valid = (lab != IGNORE_I);
    if (lab == AUX_I) lab = C_CLS - 1;
    int key = valid ? lab : IGNORE_I;
    unsigned mask = __match_any_sync(0xffffffffu, key);
    int rank = __popc(mask & ((1u << lane) - 1u));
    if (valid && rank == 0) warpHist[wid][lab] = __popc(mask);
    __syncthreads();
    if (valid) {
        int base = g_blockOffsets[blockIdx.x * C_CLS + lab];
        for (int w2 = 0; w2 < wid; w2++) base += warpHist[w2][lab];
        int slot = base + rank;
        if (slot < MEMM) g_selIdx[lab * MEMM + slot] = n;
    }
}

// one warp per selected slot: gather 256 channels, L2-normalize, write g_sel
__global__ void k_gather(const float* __restrict__ mp, const float* __restrict__ ap) {
    int wslot = blockIdx.x * 8 + (threadIdx.x >> 5);
    int lane = threadIdx.x & 31;
    if (wslot >= AROWS) return;
    int n = g_selIdx[wslot];
    float* dst = g_sel + (size_t)wslot * DIM;
    if (n < 0) {
        #pragma unroll
        for (int k = 0; k < 8; k++) dst[lane + k * 32] = 0.f;
        return;
    }
    int b = n >> 15, j = n & 32767;
    const float* src;
    if (j < 16384) {
        int h = j >> 7, w = j & 127;
        src = mp + ((size_t)b << 22) + (h << 7) + w;
    } else {
        int jj = j - 16384;
        int h = jj >> 7, w = jj & 127;
        src = ap + ((size_t)b << 22) + (h << 7) + w;
    }
    float v[8];
    float ss = 0.f;
    #pragma unroll
    for (int k = 0; k < 8; k++) {
        v[k] = src[(size_t)(lane + k * 32) << 14];
        ss += v[k] * v[k];
    }
    #pragma unroll
    for (int off = 16; off; off >>= 1) ss += __shfl_xor_sync(0xffffffffu, ss, off);
    float inv = 1.f / fmaxf(sqrtf(ss), 1e-12f);
    #pragma unroll
    for (int k = 0; k < 8; k++) dst[lane + k * 32] = v[k] * inv;
}

// one warp per slot: momentum update + renorm (or passthrough), cvalid
__global__ void k_bank(const float* __restrict__ bank) {
    int wslot = blockIdx.x * 8 + (threadIdx.x >> 5);
    int lane = threadIdx.x & 31;
    if (wslot >= AROWS) return;
    int c = wslot >> 9, m = wslot & 511;
    bool selv = (m < g_counts[c]);
    const float* br = bank + (size_t)wslot * DIM;
    float* cr = g_contras + (size_t)wslot * DIM;
    float out[8];
    float ss = 0.f;
    if (selv) {
        const float* sr = g_sel + (size_t)wslot * DIM;
        #pragma unroll
        for (int k = 0; k < 8; k++) {
            int i = lane + k * 32;
            float u = 0.999f * br[i] + 0.001f * sr[i];
            out[k] = u;
            ss += u * u;
        }
        #pragma unroll
        for (int off = 16; off; off >>= 1) ss += __shfl_xor_sync(0xffffffffu, ss, off);
        float inv = 1.f / fmaxf(sqrtf(ss), 1e-12f);
        #pragma unroll
        for (int k = 0; k < 8; k++) out[k] *= inv;
    } else {
        #pragma unroll
        for (int k = 0; k < 8; k++) {
            int i = lane + k * 32;
            out[k] = br[i];
            ss += out[k] * out[k];
        }
        #pragma unroll
        for (int off = 16; off; off >>= 1) ss += __shfl_xor_sync(0xffffffffu, ss, off);
    }
    #pragma unroll
    for (int k = 0; k < 8; k++) cr[lane + k * 32] = out[k];
    if (lane == 0) {
        float cv = (ss > 0.f) ? 1.f : 0.f;
        g_cvalid[wslot] = cv;
        if (cv > 0.f) atomicAdd(&g_cvSum[c], 1);
    }
}

// fused 128x128 tile GEMM (K=256) + exp + row reductions
__global__ void __launch_bounds__(256) k_gemm() {
    __shared__ float As[16][128];
    __shared__ float Bs[16][128];
    __shared__ float cm[128];
    __shared__ float red[128 * 16];
    int tid = threadIdx.x;
    int tx = tid & 15, ty = tid >> 4;
    int row0 = blockIdx.y * 128, col0 = blockIdx.x * 128;
    bool isPos = (row0 >> 9) == (col0 >> 9);
    if (tid < 128) cm[tid] = g_cvalid[col0 + tid];

    float acc[8][8];
    #pragma unroll
    for (int i = 0; i < 8; i++)
        #pragma unroll
        for (int j = 0; j < 8; j++) acc[i][j] = 0.f;

    const float* A = g_sel;
    const float* Bc = g_contras;
    for (int k0 = 0; k0 < DIM; k0 += 16) {
        #pragma unroll
        for (int i = 0; i < 2; i++) {
            int t = tid + i * 256;
            int r = t >> 2;
            int k4 = (t & 3) << 2;
            float4 av = *(const float4*)(A + (size_t)(row0 + r) * DIM + k0 + k4);
            As[k4 + 0][r] = av.x; As[k4 + 1][r] = av.y;
            As[k4 + 2][r] = av.z; As[k4 + 3][r] = av.w;
            float4 bv = *(const float4*)(Bc + (size_t)(col0 + r) * DIM + k0 + k4);
            Bs[k4 + 0][r] = bv.x; Bs[k4 + 1][r] = bv.y;
            Bs[k4 + 2][r] = bv.z; Bs[k4 + 3][r] = bv.w;
        }
        __syncthreads();
        #pragma unroll
        for (int kk = 0; kk < 16; kk++) {
            float a[8], b[8];
            #pragma unroll
            for (int i = 0; i < 8; i++) a[i] = As[kk][ty * 8 + i];
            #pragma unroll
            for (int j = 0; j < 8; j++) b[j] = Bs[kk][tx * 8 + j];
            #pragma unroll
            for (int i = 0; i < 8; i++)
                #pragma unroll
                for (int j = 0; j < 8; j++) acc[i][j] = fmaf(a[i], b[j], acc[i][j]);
        }
        __syncthreads();
    }

    // epilogue: scores = acc * 10; expsum (masked), possum (masked, pos tiles)
    float re[8], rp[8];
    #pragma unroll
    for (int i = 0; i < 8; i++) { re[i] = 0.f; rp[i] = 0.f; }
    #pragma unroll
    for (int i = 0; i < 8; i++)
        #pragma unroll
        for (int j = 0; j < 8; j++) {
            float cv = cm[tx * 8 + j];
            float s = acc[i][j] * 10.0f;
            re[i] += cv * __expf(s);
            rp[i] += cv * s;
        }

    #pragma unroll
    for (int i = 0; i < 8; i++) red[(ty * 8 + i) * 16 + tx] = re[i];
    __syncthreads();
    if (tid < 128) {
        float s = 0.f;
        #pragma unroll
        for (int t = 0; t < 16; t++) s += red[tid * 16 + t];
        atomicAdd(&g_rowExp[row0 + tid], s);
    }
    if (isPos) {
        __syncthreads();
        #pragma unroll
        for (int i = 0; i < 8; i++) red[(ty * 8 + i) * 16 + tx] = rp[i];
        __syncthreads();
        if (tid < 128) {
            float s = 0.f;
            #pragma unroll
            for (int t = 0; t < 16; t++) s += red[tid * 16 + t];
            atomicAdd(&g_rowPos[row0 + tid], s);
        }
    }
}

__global__ void k_loss(float* __restrict__ out) {
    __shared__ double sred[256];
    __shared__ int cred[256];
    int tid = threadIdx.x;
    double local = 0.0;
    int cnt = 0;
    for (int s = tid; s < AROWS; s += 256) {
        int c = s >> 9, m = s & 511;
        int pc = g_cvSum[c];
        if (m < g_counts[c] && pc > 0) {
            float lse = logf(g_rowExp[s]);
            float mlpp = (g_rowPos[s] - (float)pc * lse) / (float)pc;
            local += (double)mlpp;
            cnt++;
        }
    }
    sred[tid] = local;
    cred[tid] = cnt;
    __syncthreads();
    for (int off = 128; off; off >>= 1) {
        if (tid < off) {
            sred[tid] += sred[tid + off];
            cred[tid] += cred[tid + off];
        }
        __syncthreads();
    }
    if (tid == 0) {
        int n = cred[0] > 0 ? cred[0] : 1;
        out[0] = (float)(-sred[0] / (double)n);
    }
}

// ------------------------------- launcher ------------------------------------
extern "C" void kernel_launch(void* const* d_in, const int* in_sizes, int n_in,
                              void* d_out, int out_size) {
    const float* mp   = (const float*)d_in[0];   // main_proj [4,256,128,128]
    const int*   mg   = (const int*)d_in[1];     // main_gt   [4,512,512]
    const float* ap   = (const float*)d_in[2];   // aux_proj  [4,256,128,128]
    const int*   ag   = (const int*)d_in[3];     // aux_gt    [4,512,512]
    const float* bank = (const float*)d_in[4];   // memory_bank [20,512,256]
    float* out = (float*)d_out;

    k_init<<<(AROWS + 255) / 256, 256>>>();
    k_count<<<NBLK, SELBLK>>>(mg, ag);
    k_scan<<<1, 32>>>();
    k_select<<<NBLK, SELBLK>>>(mg, ag);
    k_gather<<<AROWS / 8, 256>>>(mp, ap);
    k_bank<<<AROWS / 8, 256>>>(bank);
    dim3 g(AROWS / 128, AROWS / 128);
    k_gemm<<<g, 256>>>();
    k_loss<<<1, 256>>>(out);
}

// round 3
// speedup vs baseline: 2.2519x; 2.2519x over previous
#include <cuda_runtime.h>
#include <math.h>
#include <stdint.h>

// Problem constants
#define NPIX      131072          // 4 * (16384 main + 16384 aux)
#define SELBLK    512
#define NBLK      (NPIX / SELBLK) // 256
#define C_CLS     20
#define MEMM      512
#define AROWS     (C_CLS * MEMM)  // 10240
#define DIM       256
#define IGNORE_I  255
#define AUX_I     254

#define PADL      136             // smem row stride (floats), conflict-free frags

// dynamic smem layout for GEMM kernel (bytes)
#define SMO_A     0
#define SMO_B     34816           // 2*32*136*4
#define SMO_CV    69632
#define SMO_RE    70144
#define SMO_RP    70656
#define SM_TOTAL  71168

// -------- persistent scratch ------------------------------------------------
__device__ int   g_blockCounts[NBLK * C_CLS];
__device__ int   g_blockOffsets[NBLK * C_CLS];
__device__ int   g_counts[C_CLS];
__device__ int   g_selIdx[AROWS];
__device__ float g_sel[AROWS * DIM];
__device__ float g_contras[AROWS * DIM];
__device__ float g_cvalid[AROWS];
__device__ int   g_cvSum[C_CLS];
__device__ float g_rowExp[AROWS];
__device__ float g_rowPos[AROWS];

// ----------------------------- helpers --------------------------------------
__device__ __forceinline__ uint32_t f2tf32(float v) {
    uint32_t u;
    asm("cvt.rna.tf32.f32 %0, %1;" : "=r"(u) : "f"(v));
    return u;
}

__device__ __forceinline__ void mma_tf32(float c[4], uint32_t a0, uint32_t a1,
                                         uint32_t a2, uint32_t a3,
                                         uint32_t b0, uint32_t b1) {
    asm volatile(
        "mma.sync.aligned.m16n8k8.row.col.f32.tf32.tf32.f32 "
        "{%0,%1,%2,%3}, {%4,%5,%6,%7}, {%8,%9}, {%0,%1,%2,%3};"
        : "+f"(c[0]), "+f"(c[1]), "+f"(c[2]), "+f"(c[3])
        : "r"(a0), "r"(a1), "r"(a2), "r"(a3), "r"(b0), "r"(b1));
}

__device__ __forceinline__ int pix_label(int n, const int* __restrict__ mg,
                                         const int* __restrict__ ag) {
    int b = n >> 15;
    int j = n & 32767;
    int lab;
    if (j < 16384) {
        int h = j >> 7, w = j & 127;
        lab = mg[(b << 18) + (h << 11) + (w << 2)];
    } else {
        int jj = j - 16384;
        int h = jj >> 7, w = jj & 127;
        lab = ag[(b << 18) + (h << 11) + (w << 2)];
    }
    return lab;
}

// ------------------------------ prep kernels --------------------------------
__global__ void k_init() {
    int t = blockIdx.x * blockDim.x + threadIdx.x;
    if (t < AROWS) {
        g_selIdx[t] = -1;
        g_rowExp[t] = 0.f;
        g_rowPos[t] = 0.f;
    }
    if (t < C_CLS) g_cvSum[t] = 0;
}

__global__ void k_count(const int* __restrict__ mg, const int* __restrict__ ag) {
    __shared__ int hist[C_CLS];
    if (threadIdx.x < C_CLS) hist[threadIdx.x] = 0;
    __syncthreads();
    int n = blockIdx.x * SELBLK + threadIdx.x;
    int lab = pix_label(n, mg, ag);
    if (lab != IGNORE_I) {
        if (lab == AUX_I) lab = C_CLS - 1;
        atomicAdd(&hist[lab], 1);
    }
    __syncthreads();
    if (threadIdx.x < C_CLS)
        g_blockCounts[blockIdx.x * C_CLS + threadIdx.x] = hist[threadIdx.x];
}

__global__ void k_scan() {
    int c = threadIdx.x;
    if (c >= C_CLS) return;
    int run = 0;
    for (int b = 0; b < NBLK; b++) {
        int t = g_blockCounts[b * C_CLS + c];
        g_blockOffsets[b * C_CLS + c] = run;
        run += t;
    }
    g_counts[c] = run;
}

__global__ void k_select(const int* __restrict__ mg, const int* __restrict__ ag) {
    __shared__ int warpHist[16][C_CLS];
    int tid = threadIdx.x, wid = tid >> 5, lane = tid & 31;
    for (int i = tid; i < 16 * C_CLS; i += SELBLK) ((int*)warpHist)[i] = 0;
    __syncthreads();
    int n = blockIdx.x * SELBLK + tid;
    int lab = pix_label(n, mg, ag);
    bool valid = (lab != IGNORE_I);
    if (lab == AUX_I) lab = C_CLS - 1;
    int key = valid ? lab : IGNORE_I;
    unsigned mask = __match_any_sync(0xffffffffu, key);
    int rank = __popc(mask & ((1u << lane) - 1u));
    if (valid && rank == 0) warpHist[wid][lab] = __popc(mask);
    __syncthreads();
    if (valid) {
        int base = g_blockOffsets[blockIdx.x * C_CLS + lab];
        for (int w2 = 0; w2 < wid; w2++) base += warpHist[w2][lab];
        int slot = base + rank;
        if (slot < MEMM) g_selIdx[lab * MEMM + slot] = n;
    }
}

__global__ void k_gather(const float* __restrict__ mp, const float* __restrict__ ap) {
    int wslot = blockIdx.x * 8 + (threadIdx.x >> 5);
    int lane = threadIdx.x & 31;
    if (wslot >= AROWS) return;
    int n = g_selIdx[wslot];
    float* dst = g_sel + (size_t)wslot * DIM;
    if (n < 0) {
        #pragma unroll
        for (int k = 0; k < 8; k++) dst[lane + k * 32] = 0.f;
        return;
    }
    int b = n >> 15, j = n & 32767;
    const float* src;
    if (j < 16384) {
        int h = j >> 7, w = j & 127;
        src = mp + ((size_t)b << 22) + (h << 7) + w;
    } else {
        int jj = j - 16384;
        int h = jj >> 7, w = jj & 127;
        src = ap + ((size_t)b << 22) + (h << 7) + w;
    }
    float v[8];
    float ss = 0.f;
    #pragma unroll
    for (int k = 0; k < 8; k++) {
        v[k] = src[(size_t)(lane + k * 32) << 14];
        ss += v[k] * v[k];
    }
    #pragma unroll
    for (int off = 16; off; off >>= 1) ss += __shfl_xor_sync(0xffffffffu, ss, off);
    float inv = 1.f / fmaxf(sqrtf(ss), 1e-12f);
    #pragma unroll
    for (int k = 0; k < 8; k++) dst[lane + k * 32] = v[k] * inv;
}

__global__ void k_bank(const float* __restrict__ bank) {
    int wslot = blockIdx.x * 8 + (threadIdx.x >> 5);
    int lane = threadIdx.x & 31;
    if (wslot >= AROWS) return;
    int c = wslot >> 9, m = wslot & 511;
    bool selv = (m < g_counts[c]);
    const float* br = bank + (size_t)wslot * DIM;
    float* cr = g_contras + (size_t)wslot * DIM;
    float out[8];
    float ss = 0.f;
    if (selv) {
        const float* sr = g_sel + (size_t)wslot * DIM;
        #pragma unroll
        for (int k = 0; k < 8; k++) {
            int i = lane + k * 32;
            float u = 0.999f * br[i] + 0.001f * sr[i];
            out[k] = u;
            ss += u * u;
        }
        #pragma unroll
        for (int off = 16; off; off >>= 1) ss += __shfl_xor_sync(0xffffffffu, ss, off);
        float inv = 1.f / fmaxf(sqrtf(ss), 1e-12f);
        #pragma unroll
        for (int k = 0; k < 8; k++) out[k] *= inv;
    } else {
        #pragma unroll
        for (int k = 0; k < 8; k++) {
            int i = lane + k * 32;
            out[k] = br[i];
            ss += out[k] * out[k];
        }
        #pragma unroll
        for (int off = 16; off; off >>= 1) ss += __shfl_xor_sync(0xffffffffu, ss, off);
    }
    #pragma unroll
    for (int k = 0; k < 8; k++) cr[lane + k * 32] = out[k];
    if (lane == 0) {
        float cv = (ss > 0.f) ? 1.f : 0.f;
        g_cvalid[wslot] = cv;
        if (cv > 0.f) atomicAdd(&g_cvSum[c], 1);
    }
}

// ------------------- mma.sync tf32 GEMM + fused epilogue ---------------------
// CTA: 128x128 output tile, K=256 in 8 double-buffered stages of 32.
// 8 warps: 2 (row) x 4 (col), each warp 64x32 via 4x4 m16n8k8 fragments.
__global__ void __launch_bounds__(256, 1) k_gemm_mma() {
    extern __shared__ char sm[];
    float* As = (float*)(sm + SMO_A);    // [2][32][PADL]
    float* Bs = (float*)(sm + SMO_B);    // [2][32][PADL]
    float* cvs  = (float*)(sm + SMO_CV); // [128]
    float* rowE = (float*)(sm + SMO_RE); // [128]
    float* rowP = (float*)(sm + SMO_RP); // [128]

    const int tid = threadIdx.x, lane = tid & 31, wid = tid >> 5;
    const int tig = lane & 3, grp = lane >> 2;
    const int wr = wid >> 2, wc = wid & 3;
    const int row0 = blockIdx.y * 128, col0 = blockIdx.x * 128;
    const float posf = ((row0 >> 9) == (col0 >> 9)) ? 1.f : 0.f;

    if (tid < 128) {
        cvs[tid]  = g_cvalid[col0 + tid];
        rowE[tid] = 0.f;
        rowP[tid] = 0.f;
    }

    float c[4][4][4];
    #pragma unroll
    for (int mi = 0; mi < 4; mi++)
        #pragma unroll
        for (int ni = 0; ni < 4; ni++)
            #pragma unroll
            for (int q = 0; q < 4; q++) c[mi][ni][q] = 0.f;

    const float* Ag = g_sel + (size_t)row0 * DIM;
    const float* Bg = g_contras + (size_t)col0 * DIM;

    // per-thread staging: 4 float4 of A + 4 float4 of B per stage
    const int sr = tid >> 3;             // base row for staging (0..31)
    const int sl4 = (tid & 7) << 2;      // k-offset within stage (0,4,...,28)

    uint32_t ra[4][4], rb[4][4];

    // ---- load stage 0 into regs ----
    #pragma unroll
    for (int q = 0; q < 4; q++) {
        int r = sr + q * 32;
        float4 va = *(const float4*)(Ag + (size_t)r * DIM + sl4);
        ra[q][0] = f2tf32(va.x); ra[q][1] = f2tf32(va.y);
        ra[q][2] = f2tf32(va.z); ra[q][3] = f2tf32(va.w);
        float4 vb = *(const float4*)(Bg + (size_t)r * DIM + sl4);
        rb[q][0] = f2tf32(vb.x); rb[q][1] = f2tf32(vb.y);
        rb[q][2] = f2tf32(vb.z); rb[q][3] = f2tf32(vb.w);
    }
    // store stage 0
    #pragma unroll
    for (int q = 0; q < 4; q++) {
        int r = sr + q * 32;
        #pragma unroll
        for (int j = 0; j < 4; j++) {
            As[(sl4 + j) * PADL + r] = __uint_as_float(ra[q][j]);
            Bs[(sl4 + j) * PADL + r] = __uint_as_float(rb[q][j]);
        }
    }
    __syncthreads();

    for (int s = 0; s < 8; s++) {
        const int buf = s & 1;
        // prefetch next stage into regs
        if (s < 7) {
            const int ks = (s + 1) * 32;
            #pragma unroll
            for (int q = 0; q < 4; q++) {
                int r = sr + q * 32;
                float4 va = *(const float4*)(Ag + (size_t)r * DIM + ks + sl4);
                ra[q][0] = f2tf32(va.x); ra[q][1] = f2tf32(va.y);
                ra[q][2] = f2tf32(va.z); ra[q][3] = f2tf32(va.w);
                float4 vb = *(const float4*)(Bg + (size_t)r * DIM + ks + sl4);
                rb[q][0] = f2tf32(vb.x); rb[q][1] = f2tf32(vb.y);
                rb[q][2] = f2tf32(vb.z); rb[q][3] = f2tf32(vb.w);
            }
        }
        // compute on current buffer
        const float* Ab = As + buf * 32 * PADL;
        const float* Bb = Bs + buf * 32 * PADL;
        #pragma unroll
        for (int kk = 0; kk < 32; kk += 8) {
            uint32_t bf[4][2];
            #pragma unroll
            for (int ni = 0; ni < 4; ni++) {
                int bc = wc * 32 + ni * 8 + grp;
                bf[ni][0] = __float_as_uint(Bb[(kk + tig) * PADL + bc]);
                bf[ni][1] = __float_as_uint(Bb[(kk + tig + 4) * PADL + bc]);
            }
            #pragma unroll
            for (int mi = 0; mi < 4; mi++) {
                int arow = wr * 64 + mi * 16 + grp;
                uint32_t a0 = __float_as_uint(Ab[(kk + tig) * PADL + arow]);
                uint32_t a1 = __float_as_uint(Ab[(kk + tig) * PADL + arow + 8]);
                uint32_t a2 = __float_as_uint(Ab[(kk + tig + 4) * PADL + arow]);
                uint32_t a3 = __float_as_uint(Ab[(kk + tig + 4) * PADL + arow + 8]);
                #pragma unroll
                for (int ni = 0; ni < 4; ni++)
                    mma_tf32(c[mi][ni], a0, a1, a2, a3, bf[ni][0], bf[ni][1]);
            }
        }
        __syncthreads();
        if (s < 7) {
            const int nb = (s + 1) & 1;
            #pragma unroll
            for (int q = 0; q < 4; q++) {
                int r = sr + q * 32;
                #pragma unroll
                for (int j = 0; j < 4; j++) {
                    As[(nb * 32 + sl4 + j) * PADL + r] = __uint_as_float(ra[q][j]);
                    Bs[(nb * 32 + sl4 + j) * PADL + r] = __uint_as_float(rb[q][j]);
                }
            }
            __syncthreads();
        }
    }

    // ---- epilogue: scores*10, exp + pos sums, per-row reduce ----
    #pragma unroll
    for (int mi = 0; mi < 4; mi++) {
        #pragma unroll
        for (int h = 0; h < 2; h++) {
            float e = 0.f, p = 0.f;
            #pragma unroll
            for (int ni = 0; ni < 4; ni++) {
                #pragma unroll
                for (int j = 0; j < 2; j++) {
                    int col = wc * 32 + ni * 8 + 2 * tig + j;
                    float cv = cvs[col];
                    float sc = c[mi][ni][h * 2 + j] * 10.0f;
                    e += cv * __expf(sc);
                    p += cv * sc;
                }
            }
            e += __shfl_xor_sync(0xffffffffu, e, 1);
            e += __shfl_xor_sync(0xffffffffu, e, 2);
            p += __shfl_xor_sync(0xffffffffu, p, 1);
            p += __shfl_xor_sync(0xffffffffu, p, 2);
            if (tig == 0) {
                int r = wr * 64 + mi * 16 + h * 8 + grp;
                atomicAdd(&rowE[r], e);
                atomicAdd(&rowP[r], p);
            }
        }
    }
    __syncthreads();
    if (tid < 128) {
        atomicAdd(&g_rowExp[row0 + tid], rowE[tid]);
        if (posf > 0.f) atomicAdd(&g_rowPos[row0 + tid], rowP[tid]);
    }
}

// ------------------------------- loss ----------------------------------------
__global__ void k_loss(float* __restrict__ out) {
    __shared__ double sred[256];
    __shared__ int cred[256];
    int tid = threadIdx.x;
    double local = 0.0;
    int cnt = 0;
    for (int s = tid; s < AROWS; s += 256) {
        int c = s >> 9, m = s & 511;
        int pc = g_cvSum[c];
        if (m < g_counts[c] && pc > 0) {
            float lse = logf(g_rowExp[s]);
            float mlpp = (g_rowPos[s] - (float)pc * lse) / (float)pc;
            local += (double)mlpp;
            cnt++;
        }
    }
    sred[tid] = local;
    cred[tid] = cnt;
    __syncthreads();
    for (int off = 128; off; off >>= 1) {
        if (tid < off) {
            sred[tid] += sred[tid + off];
            cred[tid] += cred[tid + off];
        }
        __syncthreads();
    }
    if (tid == 0) {
        int n = cred[0] > 0 ? cred[0] : 1;
        out[0] = (float)(-sred[0] / (double)n);
    }
}

// ------------------------------- launcher ------------------------------------
extern "C" void kernel_launch(void* const* d_in, const int* in_sizes, int n_in,
                              void* d_out, int out_size) {
    const float* mp   = (const float*)d_in[0];
    const int*   mg   = (const int*)d_in[1];
    const float* ap   = (const float*)d_in[2];
    const int*   ag   = (const int*)d_in[3];
    const float* bank = (const float*)d_in[4];
    float* out = (float*)d_out;

    cudaFuncSetAttribute(k_gemm_mma, cudaFuncAttributeMaxDynamicSharedMemorySize,
                         SM_TOTAL);

    k_init<<<(AROWS + 255) / 256, 256>>>();
    k_count<<<NBLK, SELBLK>>>(mg, ag);
    k_scan<<<1, 32>>>();
    k_select<<<NBLK, SELBLK>>>(mg, ag);
    k_gather<<<AROWS / 8, 256>>>(mp, ap);
    k_bank<<<AROWS / 8, 256>>>(bank);
    dim3 g(AROWS / 128, AROWS / 128);
    k_gemm_mma<<<g, 256, SM_TOTAL>>>();
    k_loss<<<1, 256>>>(out);
}

// round 4
// speedup vs baseline: 7.7769x; 3.4534x over previous
#include <cuda_runtime.h>
#include <cuda_bf16.h>
#include <math.h>
#include <stdint.h>

// Problem constants
#define NPIX      131072          // 4 * (16384 main + 16384 aux)
#define SELBLK    512
#define NBLK      (NPIX / SELBLK) // 256
#define C_CLS     20
#define MEMM      512
#define AROWS     (C_CLS * MEMM)  // 10240
#define DIM       256
#define IGNORE_I  255
#define AUX_I     254

#define PADB      40              // bf16 row stride in smem (80B: conflict-free LDSM)
#define STG_B     (128 * PADB)    // bf16 elems per stage buffer (10240B)

// -------- persistent scratch ------------------------------------------------
__device__ int   g_blockCounts[NBLK * C_CLS];
__device__ int   g_blockOffsets[NBLK * C_CLS];
__device__ int   g_counts[C_CLS];
__device__ int   g_selIdx[AROWS];
__device__ __nv_bfloat16 g_selb[AROWS * DIM];
__device__ __nv_bfloat16 g_contrasb[AROWS * DIM];
__device__ float g_cvalid[AROWS];
__device__ int   g_cvSum[C_CLS];
__device__ float g_rowExp[AROWS];
__device__ float g_rowPos[AROWS];

// ----------------------------- ptx helpers ----------------------------------
__device__ __forceinline__ uint32_t smem_u32(const void* p) {
    uint32_t a;
    asm("{ .reg .u64 t; cvta.to.shared.u64 t, %1; cvt.u32.u64 %0, t; }"
        : "=r"(a) : "l"(p));
    return a;
}

#define CP_ASYNC16(dst, src) \
    asm volatile("cp.async.cg.shared.global [%0], [%1], 16;" :: "r"(dst), "l"(src))
#define CP_COMMIT() asm volatile("cp.async.commit_group;" ::: "memory")
#define CP_WAIT(n)  asm volatile("cp.async.wait_group %0;" :: "n"(n) : "memory")

#define LDSM_X4(r0, r1, r2, r3, addr)                                          \
    asm volatile("ldmatrix.sync.aligned.m8n8.x4.shared.b16 {%0,%1,%2,%3}, [%4];" \
        : "=r"(r0), "=r"(r1), "=r"(r2), "=r"(r3) : "r"(addr))

__device__ __forceinline__ void mma_bf16(float c[4], const uint32_t a[4],
                                         uint32_t b0, uint32_t b1) {
    asm volatile(
        "mma.sync.aligned.m16n8k16.row.col.f32.bf16.bf16.f32 "
        "{%0,%1,%2,%3}, {%4,%5,%6,%7}, {%8,%9}, {%0,%1,%2,%3};"
        : "+f"(c[0]), "+f"(c[1]), "+f"(c[2]), "+f"(c[3])
        : "r"(a[0]), "r"(a[1]), "r"(a[2]), "r"(a[3]), "r"(b0), "r"(b1));
}

__device__ __forceinline__ int pix_label(int n, const int* __restrict__ mg,
                                         const int* __restrict__ ag) {
    int b = n >> 15;
    int j = n & 32767;
    int lab;
    if (j < 16384) {
        int h = j >> 7, w = j & 127;
        lab = mg[(b << 18) + (h << 11) + (w << 2)];
    } else {
        int jj = j - 16384;
        int h = jj >> 7, w = jj & 127;
        lab = ag[(b << 18) + (h << 11) + (w << 2)];
    }
    return lab;
}

// ------------------------------ prep kernels --------------------------------
__global__ void k_init() {
    int t = blockIdx.x * blockDim.x + threadIdx.x;
    if (t < AROWS) {
        g_selIdx[t] = -1;
        g_rowExp[t] = 0.f;
        g_rowPos[t] = 0.f;
    }
    if (t < C_CLS) g_cvSum[t] = 0;
}

__global__ void k_count(const int* __restrict__ mg, const int* __restrict__ ag) {
    __shared__ int hist[C_CLS];
    if (threadIdx.x < C_CLS) hist[threadIdx.x] = 0;
    __syncthreads();
    int n = blockIdx.x * SELBLK + threadIdx.x;
    int lab = pix_label(n, mg, ag);
    if (lab != IGNORE_I) {
        if (lab == AUX_I) lab = C_CLS - 1;
        atomicAdd(&hist[lab], 1);
    }
    __syncthreads();
    if (threadIdx.x < C_CLS)
        g_blockCounts[blockIdx.x * C_CLS + threadIdx.x] = hist[threadIdx.x];
}

__global__ void k_scan() {
    int c = threadIdx.x;
    if (c >= C_CLS) return;
    int run = 0;
    for (int b = 0; b < NBLK; b++) {
        int t = g_blockCounts[b * C_CLS + c];
        g_blockOffsets[b * C_CLS + c] = run;
        run += t;
    }
    g_counts[c] = run;
}

__global__ void k_select(const int* __restrict__ mg, const int* __restrict__ ag) {
    __shared__ int warpHist[16][C_CLS];
    int tid = threadIdx.x, wid = tid >> 5, lane = tid & 31;
    for (int i = tid; i < 16 * C_CLS; i += SELBLK) ((int*)warpHist)[i] = 0;
    __syncthreads();
    int n = blockIdx.x * SELBLK + tid;
    int lab = pix_label(n, mg, ag);
    bool valid = (lab != IGNORE_I);
    if (lab == AUX_I) lab = C_CLS - 1;
    int key = valid ? lab : IGNORE_I;
    unsigned mask = __match_any_sync(0xffffffffu, key);
    int rank = __popc(mask & ((1u << lane) - 1u));
    if (valid && rank == 0) warpHist[wid][lab] = __popc(mask);
    __syncthreads();
    if (valid) {
        int base = g_blockOffsets[blockIdx.x * C_CLS + lab];
        for (int w2 = 0; w2 < wid; w2++) base += warpHist[w2][lab];
        int slot = base + rank;
        if (slot < MEMM) g_selIdx[lab * MEMM + slot] = n;
    }
}

// gather + normalize; emit bf16 anchors
__global__ void k_gather(const float* __restrict__ mp, const float* __restrict__ ap) {
    int wslot = blockIdx.x * 8 + (threadIdx.x >> 5);
    int lane = threadIdx.x & 31;
    if (wslot >= AROWS) return;
    int n = g_selIdx[wslot];
    __nv_bfloat16* dst = g_selb + (size_t)wslot * DIM;
    if (n < 0) {
        #pragma unroll
        for (int k = 0; k < 8; k++) dst[lane + k * 32] = __float2bfloat16(0.f);
        return;
    }
    int b = n >> 15, j = n & 32767;
    const float* src;
    if (j < 16384) {
        int h = j >> 7, w = j & 127;
        src = mp + ((size_t)b << 22) + (h << 7) + w;
    } else {
        int jj = j - 16384;
        int h = jj >> 7, w = jj & 127;
        src = ap + ((size_t)b << 22) + (h << 7) + w;
    }
    float v[8];
    float ss = 0.f;
    #pragma unroll
    for (int k = 0; k < 8; k++) {
        v[k] = src[(size_t)(lane + k * 32) << 14];
        ss += v[k] * v[k];
    }
    #pragma unroll
    for (int off = 16; off; off >>= 1) ss += __shfl_xor_sync(0xffffffffu, ss, off);
    float inv = 1.f / fmaxf(sqrtf(ss), 1e-12f);
    #pragma unroll
    for (int k = 0; k < 8; k++) dst[lane + k * 32] = __float2bfloat16(v[k] * inv);
}

// momentum bank update + renorm; emit bf16 contras + cvalid
__global__ void k_bank(const float* __restrict__ bank) {
    int wslot = blockIdx.x * 8 + (threadIdx.x >> 5);
    int lane = threadIdx.x & 31;
    if (wslot >= AROWS) return;
    int c = wslot >> 9, m = wslot & 511;
    bool selv = (m < g_counts[c]);
    const float* br = bank + (size_t)wslot * DIM;
    __nv_bfloat16* cr = g_contrasb + (size_t)wslot * DIM;
    float out[8];
    float ss = 0.f;
    if (selv) {
        const __nv_bfloat16* sr = g_selb + (size_t)wslot * DIM;
        #pragma unroll
        for (int k = 0; k < 8; k++) {
            int i = lane + k * 32;
            float u = 0.999f * br[i] + 0.001f * __bfloat162float(sr[i]);
            out[k] = u;
            ss += u * u;
        }
        #pragma unroll
        for (int off = 16; off; off >>= 1) ss += __shfl_xor_sync(0xffffffffu, ss, off);
        float inv = 1.f / fmaxf(sqrtf(ss), 1e-12f);
        #pragma unroll
        for (int k = 0; k < 8; k++) out[k] *= inv;
    } else {
        #pragma unroll
        for (int k = 0; k < 8; k++) {
            int i = lane + k * 32;
            out[k] = br[i];
            ss += out[k] * out[k];
        }
        #pragma unroll
        for (int off = 16; off; off >>= 1) ss += __shfl_xor_sync(0xffffffffu, ss, off);
    }
    #pragma unroll
    for (int k = 0; k < 8; k++) cr[lane + k * 32] = __float2bfloat16(out[k]);
    if (lane == 0) {
        float cv = (ss > 0.f) ? 1.f : 0.f;
        g_cvalid[wslot] = cv;
        if (cv > 0.f) atomicAdd(&g_cvSum[c], 1);
    }
}

// -------------- bf16 mma.sync GEMM (ldmatrix + cp.async) + epilogue ----------
// CTA 128x128 tile, K=256 in 8 cp.async double-buffered stages of 32.
// 8 warps (2x4), warp 64x32 via 4x4 m16n8k16 fragments.
__global__ void __launch_bounds__(256, 2) k_gemm_bf() {
    __shared__ __nv_bfloat16 Asm[2][STG_B];
    __shared__ __nv_bfloat16 Bsm[2][STG_B];
    __shared__ float cvs[128], rowE[128], rowP[128];

    const int tid = threadIdx.x, lane = tid & 31, wid = tid >> 5;
    const int tig = lane & 3, grp = lane >> 2;
    const int wr = wid >> 2, wc = wid & 3;
    const int row0 = blockIdx.y * 128, col0 = blockIdx.x * 128;
    const bool isPos = (row0 >> 9) == (col0 >> 9);

    const uint32_t aBase = smem_u32(Asm);
    const uint32_t bBase = smem_u32(Bsm);

    if (tid < 128) {
        cvs[tid]  = g_cvalid[col0 + tid];
        rowE[tid] = 0.f;
        rowP[tid] = 0.f;
    }

    const __nv_bfloat16* Ag = g_selb + (size_t)row0 * DIM;
    const __nv_bfloat16* Bg = g_contrasb + (size_t)col0 * DIM;

    // staging coords: i in [0,512): row = i>>2, 16B segment = i&3
    const int srow0 = tid >> 2, sseg = tid & 3;

    float c[4][4][4];
    #pragma unroll
    for (int mi = 0; mi < 4; mi++)
        #pragma unroll
        for (int ni = 0; ni < 4; ni++)
            #pragma unroll
            for (int q = 0; q < 4; q++) c[mi][ni][q] = 0.f;

    // fragment addressing (per-thread constants)
    const int aRow = wr * 64 + (lane & 15);         // + mi*16
    const int aK   = (lane >> 4) * 8;               // + kc
    const int bg   = lane >> 3;
    const int bRow = wc * 32 + (bg >> 1) * 8 + (lane & 7);  // + p*16
    const int bK   = (bg & 1) * 8;                  // + kc

    // ---- prologue: stage 0 ----
    {
        #pragma unroll
        for (int h = 0; h < 2; h++) {
            int row = srow0 + h * 64;
            uint32_t dA = aBase + row * (PADB * 2) + sseg * 16;
            uint32_t dB = bBase + row * (PADB * 2) + sseg * 16;
            CP_ASYNC16(dA, (const char*)(Ag + (size_t)row * DIM + sseg * 8));
            CP_ASYNC16(dB, (const char*)(Bg + (size_t)row * DIM + sseg * 8));
        }
        CP_COMMIT();
    }

    for (int s = 0; s < 8; s++) {
        if (s + 1 < 8) {
            const int nb = (s + 1) & 1;
            const int k0 = (s + 1) * 32;
            #pragma unroll
            for (int h = 0; h < 2; h++) {
                int row = srow0 + h * 64;
                uint32_t dA = aBase + nb * (STG_B * 2) + row * (PADB * 2) + sseg * 16;
                uint32_t dB = bBase + nb * (STG_B * 2) + row * (PADB * 2) + sseg * 16;
                CP_ASYNC16(dA, (const char*)(Ag + (size_t)row * DIM + k0 + sseg * 8));
                CP_ASYNC16(dB, (const char*)(Bg + (size_t)row * DIM + k0 + sseg * 8));
            }
            CP_COMMIT();
            CP_WAIT(1);
        } else {
            CP_WAIT(0);
        }
        __syncthreads();

        const int buf = s & 1;
        const uint32_t ab = aBase + buf * (STG_B * 2);
        const uint32_t bb = bBase + buf * (STG_B * 2);
        #pragma unroll
        for (int ks = 0; ks < 2; ks++) {
            const int kc = ks * 16;
            uint32_t af[4][4];
            #pragma unroll
            for (int mi = 0; mi < 4; mi++) {
                uint32_t addr = ab + (aRow + mi * 16) * (PADB * 2) + (kc + aK) * 2;
                LDSM_X4(af[mi][0], af[mi][1], af[mi][2], af[mi][3], addr);
            }
            uint32_t bf[4][2];
            #pragma unroll
            for (int p = 0; p < 2; p++) {
                uint32_t addr = bb + (bRow + p * 16) * (PADB * 2) + (kc + bK) * 2;
                uint32_t r0, r1, r2, r3;
                LDSM_X4(r0, r1, r2, r3, addr);
                bf[2 * p][0] = r0; bf[2 * p][1] = r1;
                bf[2 * p + 1][0] = r2; bf[2 * p + 1][1] = r3;
            }
            #pragma unroll
            for (int mi = 0; mi < 4; mi++)
                #pragma unroll
                for (int ni = 0; ni < 4; ni++)
                    mma_bf16(c[mi][ni], af[mi], bf[ni][0], bf[ni][1]);
        }
        __syncthreads();
    }

    // ---- epilogue: scores*10, exp + pos sums, per-row reduce ----
    #pragma unroll
    for (int mi = 0; mi < 4; mi++) {
        #pragma unroll
        for (int h = 0; h < 2; h++) {
            float e = 0.f, p = 0.f;
            #pragma unroll
            for (int ni = 0; ni < 4; ni++) {
                #pragma unroll
                for (int j = 0; j < 2; j++) {
                    int col = wc * 32 + ni * 8 + 2 * tig + j;
                    float cv = cvs[col];
                    float sc = c[mi][ni][h * 2 + j] * 10.0f;
                    e += cv * __expf(sc);
                    p += cv * sc;
                }
            }
            e += __shfl_xor_sync(0xffffffffu, e, 1);
            e += __shfl_xor_sync(0xffffffffu, e, 2);
            p += __shfl_xor_sync(0xffffffffu, p, 1);
            p += __shfl_xor_sync(0xffffffffu, p, 2);
            if (tig == 0) {
                int r = wr * 64 + mi * 16 + h * 8 + grp;
                atomicAdd(&rowE[r], e);
                atomicAdd(&rowP[r], p);
            }
        }
    }
    __syncthreads();
    if (tid < 128) {
        atomicAdd(&g_rowExp[row0 + tid], rowE[tid]);
        if (isPos) atomicAdd(&g_rowPos[row0 + tid], rowP[tid]);
    }
}

// ------------------------------- loss ----------------------------------------
__global__ void k_loss(float* __restrict__ out) {
    __shared__ double sred[256];
    __shared__ int cred[256];
    int tid = threadIdx.x;
    double local = 0.0;
    int cnt = 0;
    for (int s = tid; s < AROWS; s += 256) {
        int c = s >> 9, m = s & 511;
        int pc = g_cvSum[c];
        if (m < g_counts[c] && pc > 0) {
            float lse = logf(g_rowExp[s]);
            float mlpp = (g_rowPos[s] - (float)pc * lse) / (float)pc;
            local += (double)mlpp;
            cnt++;
        }
    }
    sred[tid] = local;
    cred[tid] = cnt;
    __syncthreads();
    for (int off = 128; off; off >>= 1) {
        if (tid < off) {
            sred[tid] += sred[tid + off];
            cred[tid] += cred[tid + off];
        }
        __syncthreads();
    }
    if (tid == 0) {
        int n = cred[0] > 0 ? cred[0] : 1;
        out[0] = (float)(-sred[0] / (double)n);
    }
}

// ------------------------------- launcher ------------------------------------
extern "C" void kernel_launch(void* const* d_in, const int* in_sizes, int n_in,
                              void* d_out, int out_size) {
    const float* mp   = (const float*)d_in[0];
    const int*   mg   = (const int*)d_in[1];
    const float* ap   = (const float*)d_in[2];
    const int*   ag   = (const int*)d_in[3];
    const float* bank = (const float*)d_in[4];
    float* out = (float*)d_out;

    k_init<<<(AROWS + 255) / 256, 256>>>();
    k_count<<<NBLK, SELBLK>>>(mg, ag);
    k_scan<<<1, 32>>>();
    k_select<<<NBLK, SELBLK>>>(mg, ag);
    k_gather<<<AROWS / 8, 256>>>(mp, ap);
    k_bank<<<AROWS / 8, 256>>>(bank);
    dim3 g(AROWS / 128, AROWS / 128);
    k_gemm_bf<<<g, 256>>>();
    k_loss<<<1, 256>>>(out);
}

// round 5
// speedup vs baseline: 8.5457x; 1.0989x over previous
#include <cuda_runtime.h>
#include <cuda_bf16.h>
#include <math.h>
#include <stdint.h>

// Problem constants
#define NPIX      131072          // 4 * (16384 main + 16384 aux)
#define SELBLK    512
#define NBLK      (NPIX / SELBLK) // 256
#define C_CLS     20
#define MEMM      512
#define AROWS     (C_CLS * MEMM)  // 10240
#define DIM       256
#define IGNORE_I  255
#define AUX_I     254

// GEMM tiling: CTA 256x128, K stages of 32, 3-deep cp.async pipeline
#define TM        256
#define TN        128
#define PADB      40              // bf16 row stride in smem (80B, conflict-free LDSM)
#define A_STG_B   20480           // 256*80 bytes per A stage
#define B_STG_B   10240           // 128*80 bytes per B stage
#define SMO_A     0
#define SMO_B     61440           // 3*A_STG_B
#define SMO_CV    92160
#define SMO_RE    92672
#define SMO_RP    93696
#define SM_TOTAL  94720

// -------- persistent scratch ------------------------------------------------
__device__ int   g_blockCounts[NBLK * C_CLS];
__device__ int   g_blockOffsets[NBLK * C_CLS];
__device__ int   g_counts[C_CLS];
__device__ int   g_selIdx[AROWS];
__device__ __nv_bfloat16 g_selb[AROWS * DIM];
__device__ __nv_bfloat16 g_contrasb[AROWS * DIM];
__device__ float g_cvalid[AROWS];
__device__ int   g_cvSum[C_CLS];
__device__ float g_rowExp[AROWS];
__device__ float g_rowPos[AROWS];

// ----------------------------- ptx helpers ----------------------------------
__device__ __forceinline__ uint32_t smem_u32(const void* p) {
    uint32_t a;
    asm("{ .reg .u64 t; cvta.to.shared.u64 t, %1; cvt.u32.u64 %0, t; }"
        : "=r"(a) : "l"(p));
    return a;
}

#define CP_ASYNC16(dst, src) \
    asm volatile("cp.async.cg.shared.global [%0], [%1], 16;" :: "r"(dst), "l"(src))
#define CP_COMMIT() asm volatile("cp.async.commit_group;" ::: "memory")
#define CP_WAIT(n)  asm volatile("cp.async.wait_group %0;" :: "n"(n) : "memory")

#define LDSM_X4(r0, r1, r2, r3, addr)                                          \
    asm volatile("ldmatrix.sync.aligned.m8n8.x4.shared.b16 {%0,%1,%2,%3}, [%4];" \
        : "=r"(r0), "=r"(r1), "=r"(r2), "=r"(r3) : "r"(addr))

__device__ __forceinline__ void mma_bf16(float c[4], const uint32_t a[4],
                                         uint32_t b0, uint32_t b1) {
    asm volatile(
        "mma.sync.aligned.m16n8k16.row.col.f32.bf16.bf16.f32 "
        "{%0,%1,%2,%3}, {%4,%5,%6,%7}, {%8,%9}, {%0,%1,%2,%3};"
        : "+f"(c[0]), "+f"(c[1]), "+f"(c[2]), "+f"(c[3])
        : "r"(a[0]), "r"(a[1]), "r"(a[2]), "r"(a[3]), "r"(b0), "r"(b1));
}

__device__ __forceinline__ int pix_label(int n, const int* __restrict__ mg,
                                         const int* __restrict__ ag) {
    int b = n >> 15;
    int j = n & 32767;
    int lab;
    if (j < 16384) {
        int h = j >> 7, w = j & 127;
        lab = mg[(b << 18) + (h << 11) + (w << 2)];
    } else {
        int jj = j - 16384;
        int h = jj >> 7, w = jj & 127;
        lab = ag[(b << 18) + (h << 11) + (w << 2)];
    }
    return lab;
}

// ------------------------------ prep kernels --------------------------------
// fused: scratch init + per-block class histogram
__global__ void k_initcount(const int* __restrict__ mg, const int* __restrict__ ag) {
    __shared__ int hist[C_CLS];
    int tid = threadIdx.x;
    int t = blockIdx.x * SELBLK + tid;
    if (t < AROWS) {
        g_selIdx[t] = -1;
        g_rowExp[t] = 0.f;
        g_rowPos[t] = 0.f;
    }
    if (t < C_CLS) g_cvSum[t] = 0;
    if (tid < C_CLS) hist[tid] = 0;
    __syncthreads();
    int lab = pix_label(t, mg, ag);
    if (lab != IGNORE_I) {
        if (lab == AUX_I) lab = C_CLS - 1;
        atomicAdd(&hist[lab], 1);
    }
    __syncthreads();
    if (tid < C_CLS)
        g_blockCounts[blockIdx.x * C_CLS + tid] = hist[tid];
}

// warp-parallel exclusive scan: one warp per class over 256 blocks
__global__ void k_scan() {
    int w = threadIdx.x >> 5, lane = threadIdx.x & 31;
    if (w >= C_CLS) return;
    int carry = 0;
    #pragma unroll
    for (int seg = 0; seg < 8; seg++) {
        int b = seg * 32 + lane;
        int v = g_blockCounts[b * C_CLS + w];
        int incl = v;
        #pragma unroll
        for (int o = 1; o < 32; o <<= 1) {
            int tt = __shfl_up_sync(0xffffffffu, incl, o);
            if (lane >= o) incl += tt;
        }
        g_blockOffsets[b * C_CLS + w] = carry + incl - v;
        carry += __shfl_sync(0xffffffffu, incl, 31);
    }
    if (lane == 0) g_counts[w] = carry;
}

__global__ void k_select(const int* __restrict__ mg, const int* __restrict__ ag) {
    __shared__ int warpHist[16][C_CLS];
    int tid = threadIdx.x, wid = tid >> 5, lane = tid & 31;
    for (int i = tid; i < 16 * C_CLS; i += SELBLK) ((int*)warpHist)[i] = 0;
    __syncthreads();
    int n = blockIdx.x * SELBLK + tid;
    int lab = pix_label(n, mg, ag);
    bool valid = (lab != IGNORE_I);
    if (lab == AUX_I) lab = C_CLS - 1;
    int key = valid ? lab : IGNORE_I;
    unsigned mask = __match_any_sync(0xffffffffu, key);
    int rank = __popc(mask & ((1u << lane) - 1u));
    if (valid && rank == 0) warpHist[wid][lab] = __popc(mask);
    __syncthreads();
    if (valid) {
        int base = g_blockOffsets[blockIdx.x * C_CLS + lab];
        for (int w2 = 0; w2 < wid; w2++) base += warpHist[w2][lab];
        int slot = base + rank;
        if (slot < MEMM) g_selIdx[lab * MEMM + slot] = n;
    }
}

// fused gather+normalize (anchors) and momentum bank update (contras)
__global__ void k_gatherbank(const float* __restrict__ mp, const float* __restrict__ ap,
                             const float* __restrict__ bank) {
    int wslot = blockIdx.x * 8 + (threadIdx.x >> 5);
    int lane = threadIdx.x & 31;
    if (wslot >= AROWS) return;
    int n = g_selIdx[wslot];
    int c = wslot >> 9;
    __nv_bfloat16* sdst = g_selb + (size_t)wslot * DIM;
    __nv_bfloat16* cdst = g_contrasb + (size_t)wslot * DIM;
    const float* br = bank + (size_t)wslot * DIM;

    float u[8];
    float ss = 0.f;
    if (n >= 0) {
        int b = n >> 15, j = n & 32767;
        const float* src;
        if (j < 16384) {
            int h = j >> 7, w = j & 127;
            src = mp + ((size_t)b << 22) + (h << 7) + w;
        } else {
            int jj = j - 16384;
            int h = jj >> 7, w = jj & 127;
            src = ap + ((size_t)b << 22) + (h << 7) + w;
        }
        float v[8];
        float vs = 0.f;
        #pragma unroll
        for (int k = 0; k < 8; k++) {
            v[k] = src[(size_t)(lane + k * 32) << 14];
            vs += v[k] * v[k];
        }
        #pragma unroll
        for (int off = 16; off; off >>= 1) vs += __shfl_xor_sync(0xffffffffu, vs, off);
        float inv = 1.f / fmaxf(sqrtf(vs), 1e-12f);
        #pragma unroll
        for (int k = 0; k < 8; k++) {
            float s = v[k] * inv;
            sdst[lane + k * 32] = __float2bfloat16(s);
            float uu = 0.999f * br[lane + k * 32] + 0.001f * s;
            u[k] = uu;
            ss += uu * uu;
        }
        #pragma unroll
        for (int off = 16; off; off >>= 1) ss += __shfl_xor_sync(0xffffffffu, ss, off);
        float inv2 = 1.f / fmaxf(sqrtf(ss), 1e-12f);
        #pragma unroll
        for (int k = 0; k < 8; k++)
            cdst[lane + k * 32] = __float2bfloat16(u[k] * inv2);
    } else {
        #pragma unroll
        for (int k = 0; k < 8; k++) {
            sdst[lane + k * 32] = __float2bfloat16(0.f);
            float uu = br[lane + k * 32];
            u[k] = uu;
            ss += uu * uu;
            cdst[lane + k * 32] = __float2bfloat16(uu);
        }
        #pragma unroll
        for (int off = 16; off; off >>= 1) ss += __shfl_xor_sync(0xffffffffu, ss, off);
    }
    if (lane == 0) {
        float cv = (ss > 0.f) ? 1.f : 0.f;
        g_cvalid[wslot] = cv;
        if (cv > 0.f) atomicAdd(&g_cvSum[c], 1);
    }
}

// -------------- bf16 mma.sync GEMM 256x128, 3-stage cp.async -----------------
// 8 warps (4 row x 2 col), warp tile 64x64 via 4x8 m16n8k16 fragments.
__global__ void __launch_bounds__(256, 1) k_gemm_bf() {
    extern __shared__ char sm[];
    float* cvs  = (float*)(sm + SMO_CV);
    float* rowE = (float*)(sm + SMO_RE);
    float* rowP = (float*)(sm + SMO_RP);

    const int tid = threadIdx.x, lane = tid & 31, wid = tid >> 5;
    const int tig = lane & 3, grp = lane >> 2;
    const int wr = wid >> 1, wc = wid & 1;
    const int row0 = blockIdx.y * TM, col0 = blockIdx.x * TN;
    const bool isPos = (row0 >> 9) == (col0 >> 9);

    const uint32_t aBase = smem_u32(sm + SMO_A);
    const uint32_t bBase = smem_u32(sm + SMO_B);

    if (tid < 128) cvs[tid] = g_cvalid[col0 + tid];
    rowE[tid] = 0.f;
    rowP[tid] = 0.f;

    const __nv_bfloat16* Ag = g_selb + (size_t)row0 * DIM;
    const __nv_bfloat16* Bg = g_contrasb + (size_t)col0 * DIM;

    float c[4][8][4];
    #pragma unroll
    for (int mi = 0; mi < 4; mi++)
        #pragma unroll
        for (int ni = 0; ni < 8; ni++)
            #pragma unroll
            for (int q = 0; q < 4; q++) c[mi][ni][q] = 0.f;

    // fragment addressing
    const int aRow = wr * 64 + (lane & 15);          // + mi*16
    const int aK   = (lane >> 4) * 8;                // + kc
    const int bg   = lane >> 3;
    const int bRow = wc * 64 + ((bg >> 1) << 3) + (lane & 7);  // + p*16
    const int bK   = (bg & 1) * 8;                   // + kc

    // staging: A = 1024 16B chunks, B = 512 chunks; chunk -> (row, kseg)
    auto stage_load = [&](int s, int buf) {
        const int k0 = s * 32;
        #pragma unroll
        for (int t = 0; t < 4; t++) {
            int chunk = tid + t * 256;
            int row = chunk >> 2, seg = chunk & 3;
            uint32_t dA = aBase + buf * A_STG_B + row * (PADB * 2) + seg * 16;
            CP_ASYNC16(dA, (const char*)(Ag + (size_t)row * DIM + k0 + seg * 8));
        }
        #pragma unroll
        for (int t = 0; t < 2; t++) {
            int chunk = tid + t * 256;
            int row = chunk >> 2, seg = chunk & 3;
            uint32_t dB = bBase + buf * B_STG_B + row * (PADB * 2) + seg * 16;
            CP_ASYNC16(dB, (const char*)(Bg + (size_t)row * DIM + k0 + seg * 8));
        }
        CP_COMMIT();
    };

    stage_load(0, 0);
    stage_load(1, 1);

    for (int s = 0; s < 8; s++) {
        if (s + 2 < 8) {
            stage_load(s + 2, (s + 2) % 3);
            CP_WAIT(2);
        } else if (s == 6) {
            CP_WAIT(1);
        } else {
            CP_WAIT(0);
        }
        __syncthreads();

        const int buf = s % 3;
        const uint32_t ab = aBase + buf * A_STG_B;
        const uint32_t bb = bBase + buf * B_STG_B;
        #pragma unroll
        for (int ks = 0; ks < 2; ks++) {
            const int kc = ks * 16;
            uint32_t af[4][4];
            #pragma unroll
            for (int mi = 0; mi < 4; mi++) {
                uint32_t addr = ab + (aRow + mi * 16) * (PADB * 2) + (kc + aK) * 2;
                LDSM_X4(af[mi][0], af[mi][1], af[mi][2], af[mi][3], addr);
            }
            uint32_t bf[8][2];
            #pragma unroll
            for (int p = 0; p < 4; p++) {
                uint32_t addr = bb + (bRow + p * 16) * (PADB * 2) + (kc + bK) * 2;
                uint32_t r0, r1, r2, r3;
                LDSM_X4(r0, r1, r2, r3, addr);
                bf[2 * p][0] = r0; bf[2 * p][1] = r1;
                bf[2 * p + 1][0] = r2; bf[2 * p + 1][1] = r3;
            }
            #pragma unroll
            for (int mi = 0; mi < 4; mi++)
                #pragma unroll
                for (int ni = 0; ni < 8; ni++)
                    mma_bf16(c[mi][ni], af[mi], bf[ni][0], bf[ni][1]);
        }
        __syncthreads();
    }

    // ---- epilogue: scores*10, exp + pos sums, per-row reduce ----
    #pragma unroll
    for (int mi = 0; mi < 4; mi++) {
        #pragma unroll
        for (int h = 0; h < 2; h++) {
            float e = 0.f, p = 0.f;
            #pragma unroll
            for (int ni = 0; ni < 8; ni++) {
                #pragma unroll
                for (int j = 0; j < 2; j++) {
                    int col = wc * 64 + ni * 8 + 2 * tig + j;
                    float cv = cvs[col];
                    float sc = c[mi][ni][h * 2 + j] * 10.0f;
                    e += cv * __expf(sc);
                    p += cv * sc;
                }
            }
            e += __shfl_xor_sync(0xffffffffu, e, 1);
            e += __shfl_xor_sync(0xffffffffu, e, 2);
            p += __shfl_xor_sync(0xffffffffu, p, 1);
            p += __shfl_xor_sync(0xffffffffu, p, 2);
            if (tig == 0) {
                int r = wr * 64 + mi * 16 + h * 8 + grp;
                atomicAdd(&rowE[r], e);
                atomicAdd(&rowP[r], p);
            }
        }
    }
    __syncthreads();
    atomicAdd(&g_rowExp[row0 + tid], rowE[tid]);
    if (isPos) atomicAdd(&g_rowPos[row0 + tid], rowP[tid]);
}

// ------------------------------- loss ----------------------------------------
__global__ void k_loss(float* __restrict__ out) {
    __shared__ double sred[256];
    __shared__ int cred[256];
    int tid = threadIdx.x;
    double local = 0.0;
    int cnt = 0;
    for (int s = tid; s < AROWS; s += 256) {
        int c = s >> 9, m = s & 511;
        int pc = g_cvSum[c];
        if (m < g_counts[c] && pc > 0) {
            float lse = logf(g_rowExp[s]);
            float mlpp = (g_rowPos[s] - (float)pc * lse) / (float)pc;
            local += (double)mlpp;
            cnt++;
        }
    }
    sred[tid] = local;
    cred[tid] = cnt;
    __syncthreads();
    for (int off = 128; off; off >>= 1) {
        if (tid < off) {
            sred[tid] += sred[tid + off];
            cred[tid] += cred[tid + off];
        }
        __syncthreads();
    }
    if (tid == 0) {
        int n = cred[0] > 0 ? cred[0] : 1;
        out[0] = (float)(-sred[0] / (double)n);
    }
}

// ------------------------------- launcher ------------------------------------
extern "C" void kernel_launch(void* const* d_in, const int* in_sizes, int n_in,
                              void* d_out, int out_size) {
    const float* mp   = (const float*)d_in[0];
    const int*   mg   = (const int*)d_in[1];
    const float* ap   = (const float*)d_in[2];
    const int*   ag   = (const int*)d_in[3];
    const float* bank = (const float*)d_in[4];
    float* out = (float*)d_out;

    static bool attrSet = false;
    if (!attrSet) {
        cudaFuncSetAttribute(k_gemm_bf, cudaFuncAttributeMaxDynamicSharedMemorySize,
                             SM_TOTAL);
        attrSet = true;
    }

    k_initcount<<<NBLK, SELBLK>>>(mg, ag);
    k_scan<<<1, 640>>>();
    k_select<<<NBLK, SELBLK>>>(mg, ag);
    k_gatherbank<<<AROWS / 8, 256>>>(mp, ap, bank);
    dim3 g(AROWS / TN, AROWS / TM);
    k_gemm_bf<<<g, 256, SM_TOTAL>>>();
    k_loss<<<1, 256>>>(out);
}

// round 7
// speedup vs baseline: 10.9020x; 1.2757x over previous
#include <cuda_runtime.h>
#include <cuda_bf16.h>
#include <math.h>
#include <stdint.h>

// Problem constants
#define NPIX      131072          // 4 * (16384 main + 16384 aux)
#define SELBLK    512
#define NBLK      (NPIX / SELBLK) // 256
#define C_CLS     20
#define MEMM      512
#define AROWS     (C_CLS * MEMM)  // 10240
#define DIM       256
#define IGNORE_I  255
#define AUX_I     254

// Persistent GEMM tiling
#define TM        256             // band rows (A resident)
#define TN        128             // col tile
#define NCT       80              // col tiles per band
#define NTILE     3200            // 40 bands * 80
#define GRID_P    148
#define PADA_B    528             // A smem row stride bytes (256 bf16 + 16B pad)
#define PADB_B    144             // B smem row stride bytes (64 bf16 + 16B pad)
#define A_BYTES   (256 * PADA_B)  // 135168
#define B_STG     (128 * PADB_B)  // 18432
#define SMO_B     A_BYTES
#define SMO_CV    (A_BYTES + 4 * B_STG)   // 208896
#define SMEM_T    (SMO_CV + 1024)         // 209920

// -------- persistent scratch ------------------------------------------------
__device__ int   g_blockCounts[NBLK * C_CLS];
__device__ int   g_blockOffsets[NBLK * C_CLS];
__device__ int   g_counts[C_CLS];
__device__ int   g_selIdx[AROWS];
__device__ __nv_bfloat16 g_selb[AROWS * DIM];
__device__ __nv_bfloat16 g_contrasb[AROWS * DIM];
__device__ float g_cvalid[AROWS];
__device__ int   g_cvSum[C_CLS];
__device__ float g_rowExp[AROWS];
__device__ float g_rowPos[AROWS];

// ----------------------------- ptx helpers ----------------------------------
__device__ __forceinline__ uint32_t smem_u32(const void* p) {
    uint32_t a;
    asm("{ .reg .u64 t; cvta.to.shared.u64 t, %1; cvt.u32.u64 %0, t; }"
        : "=r"(a) : "l"(p));
    return a;
}

#define CP_ASYNC16(dst, src) \
    asm volatile("cp.async.cg.shared.global [%0], [%1], 16;" :: "r"(dst), "l"(src))
#define CP_ASYNC4(dst, src) \
    asm volatile("cp.async.ca.shared.global [%0], [%1], 4;" :: "r"(dst), "l"(src))
#define CP_COMMIT() asm volatile("cp.async.commit_group;" ::: "memory")
#define CP_WAIT(n)  asm volatile("cp.async.wait_group %0;" :: "n"(n) : "memory")

#define LDSM_X4(r0, r1, r2, r3, addr)                                          \
    asm volatile("ldmatrix.sync.aligned.m8n8.x4.shared.b16 {%0,%1,%2,%3}, [%4];" \
        : "=r"(r0), "=r"(r1), "=r"(r2), "=r"(r3) : "r"(addr))

__device__ __forceinline__ void mma_bf16(float c[4], const uint32_t a[4],
                                         uint32_t b0, uint32_t b1) {
    asm volatile(
        "mma.sync.aligned.m16n8k16.row.col.f32.bf16.bf16.f32 "
        "{%0,%1,%2,%3}, {%4,%5,%6,%7}, {%8,%9}, {%0,%1,%2,%3};"
        : "+f"(c[0]), "+f"(c[1]), "+f"(c[2]), "+f"(c[3])
        : "r"(a[0]), "r"(a[1]), "r"(a[2]), "r"(a[3]), "r"(b0), "r"(b1));
}

__device__ __forceinline__ int pix_label(int n, const int* __restrict__ mg,
                                         const int* __restrict__ ag) {
    int b = n >> 15;
    int j = n & 32767;
    int lab;
    if (j < 16384) {
        int h = j >> 7, w = j & 127;
        lab = mg[(b << 18) + (h << 11) + (w << 2)];
    } else {
        int jj = j - 16384;
        int h = jj >> 7, w = jj & 127;
        lab = ag[(b << 18) + (h << 11) + (w << 2)];
    }
    return lab;
}

// ------------------------------ prep kernels --------------------------------
__global__ void k_initcount(const int* __restrict__ mg, const int* __restrict__ ag) {
    __shared__ int hist[C_CLS];
    int tid = threadIdx.x;
    int t = blockIdx.x * SELBLK + tid;
    if (t < AROWS) {
        g_selIdx[t] = -1;
        g_rowExp[t] = 0.f;
        g_rowPos[t] = 0.f;
    }
    if (t < C_CLS) g_cvSum[t] = 0;
    if (tid < C_CLS) hist[tid] = 0;
    __syncthreads();
    int lab = pix_label(t, mg, ag);
    if (lab != IGNORE_I) {
        if (lab == AUX_I) lab = C_CLS - 1;
        atomicAdd(&hist[lab], 1);
    }
    __syncthreads();
    if (tid < C_CLS)
        g_blockCounts[blockIdx.x * C_CLS + tid] = hist[tid];
}

__global__ void k_scan() {
    int w = threadIdx.x >> 5, lane = threadIdx.x & 31;
    if (w >= C_CLS) return;
    int carry = 0;
    #pragma unroll
    for (int seg = 0; seg < 8; seg++) {
        int b = seg * 32 + lane;
        int v = g_blockCounts[b * C_CLS + w];
        int incl = v;
        #pragma unroll
        for (int o = 1; o < 32; o <<= 1) {
            int tt = __shfl_up_sync(0xffffffffu, incl, o);
            if (lane >= o) incl += tt;
        }
        g_blockOffsets[b * C_CLS + w] = carry + incl - v;
        carry += __shfl_sync(0xffffffffu, incl, 31);
    }
    if (lane == 0) g_counts[w] = carry;
}

__global__ void k_select(const int* __restrict__ mg, const int* __restrict__ ag) {
    __shared__ int warpHist[16][C_CLS];
    int tid = threadIdx.x, wid = tid >> 5, lane = tid & 31;
    for (int i = tid; i < 16 * C_CLS; i += SELBLK) ((int*)warpHist)[i] = 0;
    __syncthreads();
    int n = blockIdx.x * SELBLK + tid;
    int lab = pix_label(n, mg, ag);
    bool valid = (lab != IGNORE_I);
    if (lab == AUX_I) lab = C_CLS - 1;
    int key = valid ? lab : IGNORE_I;
    unsigned mask = __match_any_sync(0xffffffffu, key);
    int rank = __popc(mask & ((1u << lane) - 1u));
    if (valid && rank == 0) warpHist[wid][lab] = __popc(mask);
    __syncthreads();
    if (valid) {
        int base = g_blockOffsets[blockIdx.x * C_CLS + lab];
        for (int w2 = 0; w2 < wid; w2++) base += warpHist[w2][lab];
        int slot = base + rank;
        if (slot < MEMM) g_selIdx[lab * MEMM + slot] = n;
    }
}

__global__ void k_gatherbank(const float* __restrict__ mp, const float* __restrict__ ap,
                             const float* __restrict__ bank) {
    int wslot = blockIdx.x * 8 + (threadIdx.x >> 5);
    int lane = threadIdx.x & 31;
    if (wslot >= AROWS) return;
    int n = g_selIdx[wslot];
    int c = wslot >> 9;
    __nv_bfloat16* sdst = g_selb + (size_t)wslot * DIM;
    __nv_bfloat16* cdst = g_contrasb + (size_t)wslot * DIM;
    const float* br = bank + (size_t)wslot * DIM;

    float u[8];
    float ss = 0.f;
    if (n >= 0) {
        int b = n >> 15, j = n & 32767;
        const float* src;
        if (j < 16384) {
            int h = j >> 7, w = j & 127;
            src = mp + ((size_t)b << 22) + (h << 7) + w;
        } else {
            int jj = j - 16384;
            int h = jj >> 7, w = jj & 127;
            src = ap + ((size_t)b << 22) + (h << 7) + w;
        }
        float v[8];
        float vs = 0.f;
        #pragma unroll
        for (int k = 0; k < 8; k++) {
            v[k] = src[(size_t)(lane + k * 32) << 14];
            vs += v[k] * v[k];
        }
        #pragma unroll
        for (int off = 16; off; off >>= 1) vs += __shfl_xor_sync(0xffffffffu, vs, off);
        float inv = 1.f / fmaxf(sqrtf(vs), 1e-12f);
        #pragma unroll
        for (int k = 0; k < 8; k++) {
            float s = v[k] * inv;
            sdst[lane + k * 32] = __float2bfloat16(s);
            float uu = 0.999f * br[lane + k * 32] + 0.001f * s;
            u[k] = uu;
            ss += uu * uu;
        }
        #pragma unroll
        for (int off = 16; off; off >>= 1) ss += __shfl_xor_sync(0xffffffffu, ss, off);
        float inv2 = 1.f / fmaxf(sqrtf(ss), 1e-12f);
        #pragma unroll
        for (int k = 0; k < 8; k++)
            cdst[lane + k * 32] = __float2bfloat16(u[k] * inv2);
    } else {
        #pragma unroll
        for (int k = 0; k < 8; k++) {
            sdst[lane + k * 32] = __float2bfloat16(0.f);
            float uu = br[lane + k * 32];
            u[k] = uu;
            ss += uu * uu;
            cdst[lane + k * 32] = __float2bfloat16(uu);
        }
        #pragma unroll
        for (int off = 16; off; off >>= 1) ss += __shfl_xor_sync(0xffffffffu, ss, off);
    }
    if (lane == 0) {
        float cv = (ss > 0.f) ? 1.f : 0.f;
        g_cvalid[wslot] = cv;
        if (cv > 0.f) atomicAdd(&g_cvSum[c], 1);
    }
}

// -------------- persistent bf16 GEMM: A band resident, B streamed ------------
// 148 CTAs, 256 threads (8 warps 4x2, warp tile 64x64, frags 4x8 m16n8k16).
__global__ void __launch_bounds__(256, 1) k_gemm_p() {
    extern __shared__ char sm[];
    const uint32_t aBase = smem_u32(sm);
    const uint32_t bBase = aBase + SMO_B;
    const uint32_t cvBase = aBase + SMO_CV;
    float* cvs = (float*)(sm + SMO_CV);

    const int tid = threadIdx.x, lane = tid & 31, wid = tid >> 5;
    const int tig = lane & 3, grp = lane >> 2;
    const int wr = wid >> 1, wc = wid & 1;

    // fragment addressing constants
    const int aRow = wr * 64 + (lane & 15);
    const int aK   = (lane >> 4) * 8;
    const int bg   = lane >> 3;
    const int bRow = wc * 64 + ((bg >> 1) << 3) + (lane & 7);
    const int bK   = (bg & 1) * 8;

    int t0 = (int)(((long long)blockIdx.x * NTILE) / GRID_P);
    int t1 = (int)(((long long)(blockIdx.x + 1) * NTILE) / GRID_P);

    float c[4][8][4];
    float eAcc[4][2], pAcc[4][2];
    #pragma unroll
    for (int mi = 0; mi < 4; mi++) {
        #pragma unroll
        for (int ni = 0; ni < 8; ni++)
            #pragma unroll
            for (int q = 0; q < 4; q++) c[mi][ni][q] = 0.f;
        eAcc[mi][0] = eAcc[mi][1] = 0.f;
        pAcc[mi][0] = pAcc[mi][1] = 0.f;
    }

    int t = t0;
    while (t < t1) {
        const int band = t / NCT;
        const int ct0 = t % NCT;
        int bandEnd = (band + 1) * NCT;
        if (bandEnd > t1) bandEnd = t1;
        const int nt = bandEnd - t;
        const int total = nt * 4;
        const __nv_bfloat16* Ag = g_selb + (size_t)band * TM * DIM;

        // ---- issue A band load (135KB) ----
        #pragma unroll
        for (int i = 0; i < 32; i++) {
            int ch = tid + i * 256;
            int r = ch >> 5, seg = ch & 31;
            CP_ASYNC16(aBase + r * PADA_B + seg * 16,
                       (const char*)(Ag + (size_t)r * DIM + seg * 8));
        }
        CP_COMMIT();

        // ---- stage issue helper (B K=64 chunk: 128 rows x 8 segs) ----
        auto issue_stage = [&](int g) {
            const int ti = g >> 2, kq = g & 3;
            const int ct = ct0 + ti;
            const __nv_bfloat16* Bg =
                g_contrasb + ((size_t)ct * TN) * DIM + kq * 64;
            const uint32_t bb = bBase + (g & 3) * B_STG;
            #pragma unroll
            for (int i = 0; i < 4; i++) {
                int ch = tid + i * 256;
                int r = ch >> 3, seg = ch & 7;
                CP_ASYNC16(bb + r * PADB_B + seg * 16,
                           (const char*)(Bg + (size_t)r * DIM + seg * 8));
            }
            if (kq == 0 && tid < TN) {
                CP_ASYNC4(cvBase + (ti & 1) * 512 + tid * 4,
                          (const char*)(g_cvalid + ct * TN + tid));
            }
        };

        issue_stage(0); CP_COMMIT();
        issue_stage(1); CP_COMMIT();
        issue_stage(2); CP_COMMIT();

        for (int s = 0; s < total; s++) {
            if (s < total - 2)      { CP_WAIT(2); }
            else if (s == total - 2){ CP_WAIT(1); }
            else                    { CP_WAIT(0); }
            __syncthreads();

            // ---- compute stage s ----
            const uint32_t bb = bBase + (s & 3) * B_STG;
            const int kb = (s & 3) * 64;
            #pragma unroll
            for (int ks = 0; ks < 4; ks++) {
                const int kcA = kb + ks * 16;
                const int kcB = ks * 16;
                uint32_t af[4][4];
                #pragma unroll
                for (int mi = 0; mi < 4; mi++) {
                    uint32_t addr = aBase + (aRow + mi * 16) * PADA_B + (kcA + aK) * 2;
                    LDSM_X4(af[mi][0], af[mi][1], af[mi][2], af[mi][3], addr);
                }
                uint32_t bf[8][2];
                #pragma unroll
                for (int p = 0; p < 4; p++) {
                    uint32_t addr = bb + (bRow + p * 16) * PADB_B + (kcB + bK) * 2;
                    uint32_t r0, r1, r2, r3;
                    LDSM_X4(r0, r1, r2, r3, addr);
                    bf[2 * p][0] = r0; bf[2 * p][1] = r1;
                    bf[2 * p + 1][0] = r2; bf[2 * p + 1][1] = r3;
                }
                #pragma unroll
                for (int mi = 0; mi < 4; mi++)
                    #pragma unroll
                    for (int ni = 0; ni < 8; ni++)
                        mma_bf16(c[mi][ni], af[mi], bf[ni][0], bf[ni][1]);
            }

            // ---- per-tile epilogue into register accumulators ----
            if ((s & 3) == 3) {
                const int ti = s >> 2;
                const int ct = ct0 + ti;
                const float posf = ((band >> 1) == (ct >> 2)) ? 1.f : 0.f;
                const float* cv = cvs + (ti & 1) * 128;
                float cvr[8][2];
                #pragma unroll
                for (int ni = 0; ni < 8; ni++) {
                    cvr[ni][0] = cv[wc * 64 + ni * 8 + 2 * tig];
                    cvr[ni][1] = cv[wc * 64 + ni * 8 + 2 * tig + 1];
                }
                #pragma unroll
                for (int mi = 0; mi < 4; mi++)
                    #pragma unroll
                    for (int h = 0; h < 2; h++) {
                        float e = 0.f, p = 0.f;
                        #pragma unroll
                        for (int ni = 0; ni < 8; ni++)
                            #pragma unroll
                            for (int j = 0; j < 2; j++) {
                                float sc = c[mi][ni][h * 2 + j] * 10.0f;
                                e += cvr[ni][j] * __expf(sc);
                                p += cvr[ni][j] * sc;
                                c[mi][ni][h * 2 + j] = 0.f;
                            }
                        eAcc[mi][h] += e;
                        pAcc[mi][h] += posf * p;
                    }
            }

            // ---- prefetch stage s+3 ----
            if (s + 3 < total) {
                issue_stage(s + 3);
                CP_COMMIT();
            }
        }

        // ---- band flush: row reductions -> global atomics ----
        #pragma unroll
        for (int mi = 0; mi < 4; mi++)
            #pragma unroll
            for (int h = 0; h < 2; h++) {
                float e = eAcc[mi][h], p = pAcc[mi][h];
                e += __shfl_xor_sync(0xffffffffu, e, 1);
                e += __shfl_xor_sync(0xffffffffu, e, 2);
                p += __shfl_xor_sync(0xffffffffu, p, 1);
                p += __shfl_xor_sync(0xffffffffu, p, 2);
                if (tig == 0) {
                    int r = band * TM + wr * 64 + mi * 16 + h * 8 + grp;
                    atomicAdd(&g_rowExp[r], e);
                    atomicAdd(&g_rowPos[r], p);
                }
                eAcc[mi][h] = 0.f;
                pAcc[mi][h] = 0.f;
            }
        __syncthreads();   // protect A region before next run's loads
        t = bandEnd;
    }
}

// ------------------------------- loss ----------------------------------------
__global__ void k_loss(float* __restrict__ out) {
    __shared__ double sred[256];
    __shared__ int cred[256];
    int tid = threadIdx.x;
    double local = 0.0;
    int cnt = 0;
    for (int s = tid; s < AROWS; s += 256) {
        int c = s >> 9, m = s & 511;
        int pc = g_cvSum[c];
        if (m < g_counts[c] && pc > 0) {
            float lse = logf(g_rowExp[s]);
            float mlpp = (g_rowPos[s] - (float)pc * lse) / (float)pc;
            local += (double)mlpp;
            cnt++;
        }
    }
    sred[tid] = local;
    cred[tid] = cnt;
    __syncthreads();
    for (int off = 128; off; off >>= 1) {
        if (tid < off) {
            sred[tid] += sred[tid + off];
            cred[tid] += cred[tid + off];
        }
        __syncthreads();
    }
    if (tid == 0) {
        int n = cred[0] > 0 ? cred[0] : 1;
        out[0] = (float)(-sred[0] / (double)n);
    }
}

// ------------------------------- launcher ------------------------------------
extern "C" void kernel_launch(void* const* d_in, const int* in_sizes, int n_in,
                              void* d_out, int out_size) {
    const float* mp   = (const float*)d_in[0];
    const int*   mg   = (const int*)d_in[1];
    const float* ap   = (const float*)d_in[2];
    const int*   ag   = (const int*)d_in[3];
    const float* bank = (const float*)d_in[4];
    float* out = (float*)d_out;

    cudaFuncSetAttribute(k_gemm_p, cudaFuncAttributeMaxDynamicSharedMemorySize,
                         SMEM_T);

    k_initcount<<<NBLK, SELBLK>>>(mg, ag);
    k_scan<<<1, 640>>>();
    k_select<<<NBLK, SELBLK>>>(mg, ag);
    k_gatherbank<<<AROWS / 8, 256>>>(mp, ap, bank);
    k_gemm_p<<<GRID_P, 256, SMEM_T>>>();
    k_loss<<<1, 256>>>(out);
}